// round 3
// baseline (speedup 1.0000x reference)
#include <cuda_runtime.h>
#include <cuda_bf16.h>
#include <cstdint>

// ---------------- problem constants ----------------
#define E_      13
#define I_      13
#define H_      64
#define G_      256      // 4*H, torch gate order i,f,g,o
#define MT      256      // batch rows per CTA
#define NTILES  24       // 192 gate-cols (i,g,o) / 8
#define THREADS 512      // 16 warps, each owns 16 batch rows

// ---------------- helpers ----------------
static __device__ __forceinline__ uint32_t pack_bf16x2(float lo, float hi) {
    uint32_t r;  // first asm src -> upper half (validated in R1)
    asm("cvt.rn.bf16x2.f32 %0, %1, %2;" : "=r"(r) : "f"(hi), "f"(lo));
    return r;
}
static __device__ __forceinline__ uint32_t pack_f16x2(float lo, float hi) {
    uint32_t r;  // lo -> lower half, hi -> upper half
    asm("cvt.rn.f16x2.f32 %0, %1, %2;" : "=r"(r) : "f"(hi), "f"(lo));
    return r;
}
static __device__ __forceinline__ uint32_t tanh2(uint32_t v) {
    uint32_t y;
    asm("tanh.approx.f16x2 %0, %1;" : "=r"(y) : "r"(v));
    return y;
}
static __device__ __forceinline__ uint32_t hmul2(uint32_t a, uint32_t b) {
    uint32_t d;
    asm("mul.rn.f16x2 %0, %1, %2;" : "=r"(d) : "r"(a), "r"(b));
    return d;
}
static __device__ __forceinline__ uint32_t hfma2(uint32_t a, uint32_t b, uint32_t c) {
    uint32_t d;
    asm("fma.rn.f16x2 %0, %1, %2, %3;" : "=r"(d) : "r"(a), "r"(b), "r"(c));
    return d;
}
static __device__ __forceinline__ void unpack2(float& lo, float& hi, uint32_t v) {
    asm("{ .reg .b16 l, h;\n\t"
        "  mov.b32 {l, h}, %2;\n\t"
        "  cvt.f32.f16 %0, l;\n\t"
        "  cvt.f32.f16 %1, h; }"
        : "=f"(lo), "=f"(hi) : "r"(v));
}
#define H05 0x38003800u   // (0.5, 0.5) in f16x2

static __device__ __forceinline__ float tanh_a(float v) {
    float y;
    asm("tanh.approx.f32 %0, %1;" : "=f"(y) : "f"(v));
    return y;
}

#define MMA16816(d0,d1,d2,d3, a0,a1,a2,a3, b0,b1)                              \
    asm volatile(                                                              \
        "mma.sync.aligned.m16n8k16.row.col.f32.bf16.bf16.f32 "                 \
        "{%0,%1,%2,%3}, {%4,%5,%6,%7}, {%8,%9}, {%0,%1,%2,%3};"                \
        : "+f"(d0), "+f"(d1), "+f"(d2), "+f"(d3)                               \
        : "r"(a0), "r"(a1), "r"(a2), "r"(a3), "r"(b0), "r"(b1))

// ---------------- kernel ----------------
// Grid (E, B/256). e fastest -> 13 e-CTAs of one b-tile adjacent for L2 merging.
// CTA: 512 threads = 16 warps; warp w owns batch rows [b0+16w, b0+16w+16).
// Gate N-layout: 0-63 = i, 64-127 = g, 128-191 = o (f skipped: f*c0=0).
// i/o weight columns (and their biases) are PRE-SCALED by 0.5 so that
// sigma(x) = 0.5*tanh(x/2)+0.5 needs no extra multiply.
// K-layout (K=16): k 0-12 = x / W_ih, k 13 = ones-col / (b_ih+b_hh), 14,15 = 0.
__global__ __launch_bounds__(THREADS, 2) void MusicLSTM_kernel(
    const float* __restrict__ x,      // [B, E, I]
    const float* __restrict__ Wih,    // [E, 4H, I]
    const float* __restrict__ bih,    // [E, 4H]
    const float* __restrict__ bhh,    // [E, 4H]
    const float* __restrict__ Wlin,   // [E, H]
    const float* __restrict__ blin,   // [E]
    float* __restrict__ out)          // [B, E]
{
    __shared__ float    xs[MT * 16];             // [row][k], k padded to 16
    __shared__ uint32_t bfrag[NTILES * 32 * 2];  // prebuilt B fragments (tile, lane)
    __shared__ float    wl[H_];

    const int tid = threadIdx.x;
    const int e   = blockIdx.x;
    const int b0  = blockIdx.y * MT;

    // ---- stage x into smem ----
    for (int idx = tid; idx < MT * I_; idx += THREADS) {
        int r = idx / I_, c = idx - r * I_;
        xs[r * 16 + c] = x[(size_t)(b0 + r) * (E_ * I_) + e * I_ + c];
    }
    if (tid < MT) {                 // bias ones-column + zero pads
        xs[tid * 16 + 13] = 1.0f;
        xs[tid * 16 + 14] = 0.0f;
        xs[tid * 16 + 15] = 0.0f;
    }
    if (tid < H_) wl[tid] = Wlin[e * H_ + tid];

    // ---- prebuild B fragments (shared by all warps) ----
    // m16n8k16 B layout: lane = n_in_tile*4+tg holds
    //   reg0: (k=2tg,2tg+1), reg1: (k=2tg+8,2tg+9)
    for (int p = tid; p < NTILES * 32; p += THREADS) {
        int t  = p >> 5, ln = p & 31;
        int g  = ln >> 2, tg = ln & 3;
        int n  = t * 8 + g;
        int src = (n < 64) ? n : n + 64;          // i:0-63, g:128-191, o:192-255
        float scale = (n < 64 || n >= 128) ? 0.5f : 1.0f;   // pre-halve i & o
        const float* wrow = Wih + ((size_t)e * G_ + src) * I_;
        float bsum = (bih[e * G_ + src] + bhh[e * G_ + src]) * scale;
        float v[4];
        const int ks[4] = {2 * tg, 2 * tg + 1, 2 * tg + 8, 2 * tg + 9};
        #pragma unroll
        for (int j = 0; j < 4; j++) {
            int k = ks[j];
            v[j] = (k < I_) ? wrow[k] * scale : ((k == 13) ? bsum : 0.0f);
        }
        bfrag[p * 2 + 0] = pack_bf16x2(v[0], v[1]);
        bfrag[p * 2 + 1] = pack_bf16x2(v[2], v[3]);
    }
    __syncthreads();

    // ---- per-warp MMA + fused f16x2 epilogue ----
    const int wid = tid >> 5, ln = tid & 31;
    const int g   = ln >> 2,  tg = ln & 3;
    const int r0  = wid * 16;

    // A fragment (single K=16 step, reused across all 24 n-tiles)
    const float* rowA = &xs[(r0 + g) * 16];
    const float* rowB = &xs[(r0 + g + 8) * 16];
    float2 a00 = *(const float2*)(rowA + 2 * tg);
    float2 a10 = *(const float2*)(rowB + 2 * tg);
    float2 a01 = *(const float2*)(rowA + 2 * tg + 8);
    float2 a11 = *(const float2*)(rowB + 2 * tg + 8);
    uint32_t ra0 = pack_bf16x2(a00.x, a00.y);
    uint32_t ra1 = pack_bf16x2(a10.x, a10.y);
    uint32_t ra2 = pack_bf16x2(a01.x, a01.y);
    uint32_t ra3 = pack_bf16x2(a11.x, a11.y);

    float acc0 = 0.0f, acc1 = 0.0f;   // partial W_lin dots for rows g and g+8

    #pragma unroll
    for (int hc = 0; hc < 8; hc++) {
        const uint32_t* bi = &bfrag[(hc)      * 64 + ln * 2];
        const uint32_t* bg = &bfrag[(hc + 8)  * 64 + ln * 2];
        const uint32_t* bo = &bfrag[(hc + 16) * 64 + ln * 2];

        float di0 = 0, di1 = 0, di2 = 0, di3 = 0;   // i/2 gates
        float dg0 = 0, dg1 = 0, dg2 = 0, dg3 = 0;   // g gates
        float dq0 = 0, dq1 = 0, dq2 = 0, dq3 = 0;   // o/2 gates
        MMA16816(di0, di1, di2, di3, ra0, ra1, ra2, ra3, bi[0], bi[1]);
        MMA16816(dg0, dg1, dg2, dg3, ra0, ra1, ra2, ra3, bg[0], bg[1]);
        MMA16816(dq0, dq1, dq2, dq3, ra0, ra1, ra2, ra3, bo[0], bo[1]);

        // pack pairs (col 2tg -> lo, col 2tg+1 -> hi); rows g and g+8
        uint32_t si0 = hfma2(tanh2(pack_f16x2(di0, di1)), H05, H05);  // sigma(i) row g
        uint32_t si1 = hfma2(tanh2(pack_f16x2(di2, di3)), H05, H05);  // row g+8
        uint32_t tg0 = tanh2(pack_f16x2(dg0, dg1));
        uint32_t tg1 = tanh2(pack_f16x2(dg2, dg3));
        uint32_t so0 = hfma2(tanh2(pack_f16x2(dq0, dq1)), H05, H05);
        uint32_t so1 = hfma2(tanh2(pack_f16x2(dq2, dq3)), H05, H05);

        uint32_t h0 = hmul2(so0, tanh2(hmul2(si0, tg0)));  // sigma(o)*tanh(c), row g
        uint32_t h1 = hmul2(so1, tanh2(hmul2(si1, tg1)));  // row g+8

        float2 w = *(const float2*)&wl[hc * 8 + 2 * tg];
        float hx, hy;
        unpack2(hx, hy, h0);
        acc0 = fmaf(hx, w.x, acc0);
        acc0 = fmaf(hy, w.y, acc0);
        unpack2(hx, hy, h1);
        acc1 = fmaf(hx, w.x, acc1);
        acc1 = fmaf(hy, w.y, acc1);
    }

    // reduce across the 4 lanes of each quad (tg bits = lane bits 0,1)
    acc0 += __shfl_xor_sync(0xffffffffu, acc0, 1);
    acc0 += __shfl_xor_sync(0xffffffffu, acc0, 2);
    acc1 += __shfl_xor_sync(0xffffffffu, acc1, 1);
    acc1 += __shfl_xor_sync(0xffffffffu, acc1, 2);

    if (tg == 0) {
        float bl = __ldg(&blin[e]);
        float z0 = acc0 + bl;
        float z1 = acc1 + bl;
        out[(size_t)(b0 + r0 + g)     * E_ + e] = __fdividef(1.0f, 1.0f + __expf(-z0));
        out[(size_t)(b0 + r0 + g + 8) * E_ + e] = __fdividef(1.0f, 1.0f + __expf(-z1));
    }
}

// ---------------- launch ----------------
extern "C" void kernel_launch(void* const* d_in, const int* in_sizes, int n_in,
                              void* d_out, int out_size) {
    const float* x    = (const float*)d_in[0];
    const float* Wih  = (const float*)d_in[1];
    // d_in[2] = W_hh multiplies h0 = 0 -> unused
    const float* bih  = (const float*)d_in[3];
    const float* bhh  = (const float*)d_in[4];
    const float* Wlin = (const float*)d_in[5];
    const float* blin = (const float*)d_in[6];
    float* out = (float*)d_out;

    int Bv = in_sizes[0] / (E_ * I_);    // 131072
    dim3 grid(E_, Bv / MT);              // (13, 512)
    MusicLSTM_kernel<<<grid, THREADS>>>(x, Wih, bih, bhh, Wlin, blin, out);
}

// round 4
// speedup vs baseline: 1.5439x; 1.5439x over previous
#include <cuda_runtime.h>
#include <cuda_fp16.h>
#include <cstdint>

// ---------------- problem constants ----------------
#define E_      13
#define I_      13
#define H_      64
#define G_      256      // 4*H, torch gate order i,f,g,o
#define MT      128      // batch rows per CTA
#define NTILES  24       // 192 gate-cols (i,g,o) / 8
#define THREADS 256      // 8 warps, each owns 16 batch rows

// ---------------- helpers ----------------
static __device__ __forceinline__ uint32_t pack_f16x2(float lo, float hi) {
    uint32_t r;  // first asm src -> upper half
    asm("cvt.rn.f16x2.f32 %0, %1, %2;" : "=r"(r) : "f"(hi), "f"(lo));
    return r;
}
static __device__ __forceinline__ uint32_t tanh2(uint32_t v) {
    uint32_t y;
    asm("tanh.approx.f16x2 %0, %1;" : "=r"(y) : "r"(v));
    return y;
}
static __device__ __forceinline__ uint32_t hmul2(uint32_t a, uint32_t b) {
    uint32_t d;
    asm("mul.rn.f16x2 %0, %1, %2;" : "=r"(d) : "r"(a), "r"(b));
    return d;
}
static __device__ __forceinline__ uint32_t hfma2(uint32_t a, uint32_t b, uint32_t c) {
    uint32_t d;
    asm("fma.rn.f16x2 %0, %1, %2, %3;" : "=r"(d) : "r"(a), "r"(b), "r"(c));
    return d;
}
static __device__ __forceinline__ void unpack2(float& lo, float& hi, uint32_t v) {
    asm("{ .reg .b16 l, h;\n\t"
        "  mov.b32 {l, h}, %2;\n\t"
        "  cvt.f32.f16 %0, l;\n\t"
        "  cvt.f32.f16 %1, h; }"
        : "=f"(lo), "=f"(hi) : "r"(v));
}
#define H05 0x38003800u   // (0.5, 0.5) in f16x2

// f16-accumulate MMA: D fragment = 2 regs, each a packed f16x2 pair
// d0 = (row g,   cols 2tg,2tg+1), d1 = (row g+8, cols 2tg,2tg+1)
#define MMA16816_F16(d0,d1, a0,a1,a2,a3, b0,b1)                                \
    asm volatile(                                                              \
        "mma.sync.aligned.m16n8k16.row.col.f16.f16.f16.f16 "                   \
        "{%0,%1}, {%2,%3,%4,%5}, {%6,%7}, {%0,%1};"                            \
        : "+r"(d0), "+r"(d1)                                                   \
        : "r"(a0), "r"(a1), "r"(a2), "r"(a3), "r"(b0), "r"(b1))

// ---------------- kernel ----------------
// Grid (E, B/128). e fastest -> 13 e-CTAs of one b-tile adjacent (L2 merge).
// CTA: 256 threads = 8 warps; warp w owns batch rows [b0+16w, b0+16w+16).
// Gate N-layout: 0-63 = i, 64-127 = g, 128-191 = o (f skipped: f*c0=0).
// i/o weight columns (and biases) PRE-SCALED by 0.5: sigma(x)=0.5*tanh(x/2)+0.5.
// K-layout (K=16): k 0-12 = x / W_ih, k 13 = ones-col / (b_ih+b_hh), 14,15 = 0.
__global__ __launch_bounds__(THREADS) void MusicLSTM_kernel(
    const float* __restrict__ x,      // [B, E, I]
    const float* __restrict__ Wih,    // [E, 4H, I]
    const float* __restrict__ bih,    // [E, 4H]
    const float* __restrict__ bhh,    // [E, 4H]
    const float* __restrict__ Wlin,   // [E, H]
    const float* __restrict__ blin,   // [E]
    float* __restrict__ out)          // [B, E]
{
    __shared__ float    xs[MT * 16];             // [row][k], k padded to 16
    __shared__ uint32_t bfrag[NTILES * 32 * 2];  // prebuilt f16x2 B fragments
    __shared__ float    wl[H_];

    const int tid = threadIdx.x;
    const int e   = blockIdx.x;
    const int b0  = blockIdx.y * MT;

    // ---- stage x into smem ----
    for (int idx = tid; idx < MT * I_; idx += THREADS) {
        int r = idx / I_, c = idx - r * I_;
        xs[r * 16 + c] = x[(size_t)(b0 + r) * (E_ * I_) + e * I_ + c];
    }
    if (tid < MT) {                 // bias ones-column + zero pads
        xs[tid * 16 + 13] = 1.0f;
        xs[tid * 16 + 14] = 0.0f;
        xs[tid * 16 + 15] = 0.0f;
    }
    if (tid < H_) wl[tid] = Wlin[e * H_ + tid];

    // ---- prebuild B fragments (f16, shared by all 8 warps) ----
    // m16n8k16 B layout: lane = n_in_tile*4+tg holds
    //   reg0: (k=2tg,2tg+1), reg1: (k=2tg+8,2tg+9)
    for (int p = tid; p < NTILES * 32; p += THREADS) {
        int t  = p >> 5, ln = p & 31;
        int g  = ln >> 2, tg = ln & 3;
        int n  = t * 8 + g;
        int src = (n < 64) ? n : n + 64;          // i:0-63, g:128-191, o:192-255
        float scale = (n < 64 || n >= 128) ? 0.5f : 1.0f;   // pre-halve i & o
        const float* wrow = Wih + ((size_t)e * G_ + src) * I_;
        float bsum = (bih[e * G_ + src] + bhh[e * G_ + src]) * scale;
        float v[4];
        const int ks[4] = {2 * tg, 2 * tg + 1, 2 * tg + 8, 2 * tg + 9};
        #pragma unroll
        for (int j = 0; j < 4; j++) {
            int k = ks[j];
            v[j] = (k < I_) ? wrow[k] * scale : ((k == 13) ? bsum : 0.0f);
        }
        bfrag[p * 2 + 0] = pack_f16x2(v[0], v[1]);
        bfrag[p * 2 + 1] = pack_f16x2(v[2], v[3]);
    }
    __syncthreads();

    // ---- per-warp MMA + fused f16x2 epilogue ----
    const int wid = tid >> 5, ln = tid & 31;
    const int g   = ln >> 2,  tg = ln & 3;
    const int r0  = wid * 16;

    // A fragment in f16 (single K=16 step, reused across all 24 n-tiles)
    const float* rowA = &xs[(r0 + g) * 16];
    const float* rowB = &xs[(r0 + g + 8) * 16];
    float2 a00 = *(const float2*)(rowA + 2 * tg);
    float2 a10 = *(const float2*)(rowB + 2 * tg);
    float2 a01 = *(const float2*)(rowA + 2 * tg + 8);
    float2 a11 = *(const float2*)(rowB + 2 * tg + 8);
    uint32_t ra0 = pack_f16x2(a00.x, a00.y);
    uint32_t ra1 = pack_f16x2(a10.x, a10.y);
    uint32_t ra2 = pack_f16x2(a01.x, a01.y);
    uint32_t ra3 = pack_f16x2(a11.x, a11.y);

    float acc0 = 0.0f, acc1 = 0.0f;   // partial W_lin dots for rows g and g+8

    #pragma unroll
    for (int hc = 0; hc < 8; hc++) {
        const uint32_t* bi = &bfrag[(hc)      * 64 + ln * 2];
        const uint32_t* bg = &bfrag[(hc + 8)  * 64 + ln * 2];
        const uint32_t* bo = &bfrag[(hc + 16) * 64 + ln * 2];

        uint32_t di0 = 0, di1 = 0;   // i/2 gates (rows g, g+8), packed pairs
        uint32_t dg0 = 0, dg1 = 0;   // g gates
        uint32_t dq0 = 0, dq1 = 0;   // o/2 gates
        MMA16816_F16(di0, di1, ra0, ra1, ra2, ra3, bi[0], bi[1]);
        MMA16816_F16(dg0, dg1, ra0, ra1, ra2, ra3, bg[0], bg[1]);
        MMA16816_F16(dq0, dq1, ra0, ra1, ra2, ra3, bo[0], bo[1]);

        // sigma(i) = 0.5*tanh(i/2)+0.5 (pre-scale folded into weights)
        uint32_t si0 = hfma2(tanh2(di0), H05, H05);
        uint32_t si1 = hfma2(tanh2(di1), H05, H05);
        uint32_t tg0 = tanh2(dg0);
        uint32_t tg1 = tanh2(dg1);
        uint32_t so0 = hfma2(tanh2(dq0), H05, H05);
        uint32_t so1 = hfma2(tanh2(dq1), H05, H05);

        uint32_t h0 = hmul2(so0, tanh2(hmul2(si0, tg0)));  // row g
        uint32_t h1 = hmul2(so1, tanh2(hmul2(si1, tg1)));  // row g+8

        float2 w = *(const float2*)&wl[hc * 8 + 2 * tg];
        float hx, hy;
        unpack2(hx, hy, h0);
        acc0 = fmaf(hx, w.x, acc0);
        acc0 = fmaf(hy, w.y, acc0);
        unpack2(hx, hy, h1);
        acc1 = fmaf(hx, w.x, acc1);
        acc1 = fmaf(hy, w.y, acc1);
    }

    // reduce across the 4 lanes of each quad (tg bits = lane bits 0,1)
    acc0 += __shfl_xor_sync(0xffffffffu, acc0, 1);
    acc0 += __shfl_xor_sync(0xffffffffu, acc0, 2);
    acc1 += __shfl_xor_sync(0xffffffffu, acc1, 1);
    acc1 += __shfl_xor_sync(0xffffffffu, acc1, 2);

    if (tg == 0) {
        float bl = __ldg(&blin[e]);
        float z0 = acc0 + bl;
        float z1 = acc1 + bl;
        out[(size_t)(b0 + r0 + g)     * E_ + e] = __fdividef(1.0f, 1.0f + __expf(-z0));
        out[(size_t)(b0 + r0 + g + 8) * E_ + e] = __fdividef(1.0f, 1.0f + __expf(-z1));
    }
}

// ---------------- launch ----------------
extern "C" void kernel_launch(void* const* d_in, const int* in_sizes, int n_in,
                              void* d_out, int out_size) {
    const float* x    = (const float*)d_in[0];
    const float* Wih  = (const float*)d_in[1];
    // d_in[2] = W_hh multiplies h0 = 0 -> unused
    const float* bih  = (const float*)d_in[3];
    const float* bhh  = (const float*)d_in[4];
    const float* Wlin = (const float*)d_in[5];
    const float* blin = (const float*)d_in[6];
    float* out = (float*)d_out;

    int Bv = in_sizes[0] / (E_ * I_);    // 131072
    dim3 grid(E_, Bv / MT);              // (13, 1024)
    MusicLSTM_kernel<<<grid, THREADS>>>(x, Wih, bih, bhh, Wlin, blin, out);
}